// round 2
// baseline (speedup 1.0000x reference)
#include <cuda_runtime.h>

#define B   64
#define P   196
#define ENC 2048
#define H   1024
#define AA  1024
#define EE  512
#define VV  10000
#define TC  32
#define T   31

// ---- output layout: concat(predictions, alphas, caps, dec_lens, ind), float32
#define OFF_PRED  0ULL
#define OFF_ALPHA 19840000ULL
#define OFF_CAPS  20228864ULL
#define OFF_DLEN  20230912ULL
#define OFF_IND   20230976ULL

// ---- device scratch (static globals: allowed; no runtime allocation)
__device__ int   g_ind[B];
__device__ int   g_dlen[B];
__device__ int   g_caps[B * TC];
__device__ float g_mean[B * ENC];
__device__ float g_h[B * H];
__device__ float g_c[B * H];
__device__ float g_encatt[(size_t)B * P * AA];   // 51.4 MB
__device__ float g_part1[B * 7168];              // [dec | beta | hh] = h @ [Wdec;Wbeta;Whh]^T (no bias)
__device__ float g_alog[B * P];
__device__ float g_alpha[B * P];
__device__ float g_awe[B * ENC];
__device__ float g_part2[2 * B * 4096];          // split-K=2 partials of x @ W_ih^T

__device__ __forceinline__ float sigf(float x) { return 1.f / (1.f + expf(-x)); }

// ============================================================
// sort: stable argsort of -lengths; emit ind/dec_lens/caps tail of output
// ============================================================
__global__ void k_sort(const int* __restrict__ lengths,
                       const int* __restrict__ caps_in,
                       float* __restrict__ out) {
    int i = threadIdx.x;           // 0..63
    int li = lengths[i];
    int r = 0;
    for (int j = 0; j < B; j++) {
        int lj = lengths[j];
        if (lj > li || (lj == li && j < i)) r++;
    }
    g_ind[r]  = i;
    g_dlen[r] = li - 1;
    out[OFF_DLEN + r] = (float)(li - 1);
    out[OFF_IND + r]  = (float)i;
    for (int t = 0; t < TC; t++) {
        int cv = caps_in[i * TC + t];
        g_caps[r * TC + t] = cv;
        out[OFF_CAPS + (size_t)r * TC + t] = (float)cv;
    }
}

// ============================================================
// mean over P of sorted enc_out
// ============================================================
__global__ __launch_bounds__(256) void k_mean(const float* __restrict__ enc_out) {
    int b = blockIdx.x >> 3, ch = blockIdx.x & 7;
    int e = ch * 256 + threadIdx.x;
    const float* src = enc_out + (size_t)g_ind[b] * P * ENC + e;
    float s = 0.f;
    #pragma unroll 4
    for (int p = 0; p < P; p++) s += src[(size_t)p * ENC];
    g_mean[(size_t)b * ENC + e] = s * (1.f / 196.f);
}

// ============================================================
// generic 64xN tiled fp32 GEMM:  C[M,N] = A[M,K] @ W[N,K]^T (+bias)
// block tile 64x64, KT=32, 256 threads, 4x4 microtile
// ============================================================
enum { AM_PLAIN = 0, AM_ENC = 1, AM_X = 2 };   // A source
enum { BM_PLAIN = 0, BM_G1 = 2 };              // W source
enum { OM_PART = 0, OM_PLAIN = 1, OM_PRED = 2 };

template <int AMODE, int BMODE, int OMODE>
__global__ __launch_bounds__(256) void gemm64(
    const float* __restrict__ A, int lda,
    const float* __restrict__ encsrc,
    const float* __restrict__ embp, const float* __restrict__ awep, int t,
    const float* __restrict__ W0, const float* __restrict__ W1, const float* __restrict__ W2,
    const float* __restrict__ bias,
    float* __restrict__ C, int N, int K)
{
    __shared__ float As[32][64];
    __shared__ float Bs[32][64];
    __shared__ int   srow[64];

    const int tid = threadIdx.x;
    const int tx = tid & 15, ty = tid >> 4;
    const int nbase = blockIdx.x * 64;
    const int mbase = blockIdx.y * 64;
    const int S = gridDim.z;
    const int kLen = K / S;
    const int kStart = blockIdx.z * kLen;

    if (AMODE == AM_ENC) {
        if (tid < 64) { int m = mbase + tid; srow[tid] = g_ind[m / 196] * 196 + (m % 196); }
        __syncthreads();
    } else if (AMODE == AM_X) {
        if (tid < 64) srow[tid] = g_caps[(mbase + tid) * TC + t];
        __syncthreads();
    }

    float acc[4][4];
    #pragma unroll
    for (int i = 0; i < 4; i++)
        #pragma unroll
        for (int j = 0; j < 4; j++) acc[i][j] = 0.f;

    const int la = tid >> 2;          // 0..63: row within tile that this thread loads
    const int lk = (tid & 3) * 8;     // k offset: 0,8,16,24

    for (int k0 = kStart; k0 < kStart + kLen; k0 += 32) {
        // ---- fetch A fragment (row mbase+la, k = k0+lk .. +7)
        float4 a0, a1;
        {
            int kg = k0 + lk;
            if (AMODE == AM_PLAIN) {
                const float* p = A + (size_t)(mbase + la) * lda + kg;
                a0 = *(const float4*)p; a1 = *(const float4*)(p + 4);
            } else if (AMODE == AM_ENC) {
                const float* p = encsrc + (size_t)srow[la] * ENC + kg;
                a0 = *(const float4*)p; a1 = *(const float4*)(p + 4);
            } else { // AM_X: [emb_t | awe]
                const float* p0 = (kg < EE) ? (embp + (size_t)srow[la] * EE + kg)
                                            : (awep + (size_t)(mbase + la) * ENC + (kg - EE));
                a0 = *(const float4*)p0;
                int kg1 = kg + 4;
                const float* p1 = (kg1 < EE) ? (embp + (size_t)srow[la] * EE + kg1)
                                             : (awep + (size_t)(mbase + la) * ENC + (kg1 - EE));
                a1 = *(const float4*)p1;
            }
        }
        // ---- fetch W fragment (row nbase+la, k = k0+lk .. +7)
        float4 b0, b1;
        {
            int n = nbase + la;
            int kg = k0 + lk;
            const float* wp = nullptr;
            if (BMODE == BM_PLAIN) {
                if (n < N) wp = W0 + (size_t)n * K + kg;
            } else { // BM_G1: rows [0,1024)=Wdec, [1024,3072)=Wbeta, [3072,7168)=Whh, all K=1024
                if (n < 1024)      wp = W0 + (size_t)n * 1024 + kg;
                else if (n < 3072) wp = W1 + (size_t)(n - 1024) * 1024 + kg;
                else               wp = W2 + (size_t)(n - 3072) * 1024 + kg;
            }
            if (wp) { b0 = *(const float4*)wp; b1 = *(const float4*)(wp + 4); }
            else    { b0 = make_float4(0.f, 0.f, 0.f, 0.f); b1 = b0; }
        }
        __syncthreads();   // protect previous iteration's reads
        As[lk + 0][la] = a0.x; As[lk + 1][la] = a0.y; As[lk + 2][la] = a0.z; As[lk + 3][la] = a0.w;
        As[lk + 4][la] = a1.x; As[lk + 5][la] = a1.y; As[lk + 6][la] = a1.z; As[lk + 7][la] = a1.w;
        Bs[lk + 0][la] = b0.x; Bs[lk + 1][la] = b0.y; Bs[lk + 2][la] = b0.z; Bs[lk + 3][la] = b0.w;
        Bs[lk + 4][la] = b1.x; Bs[lk + 5][la] = b1.y; Bs[lk + 6][la] = b1.z; Bs[lk + 7][la] = b1.w;
        __syncthreads();
        #pragma unroll
        for (int kk = 0; kk < 32; kk++) {
            float4 av = *(const float4*)&As[kk][ty * 4];
            float4 bv = *(const float4*)&Bs[kk][tx * 4];
            acc[0][0] += av.x * bv.x; acc[0][1] += av.x * bv.y; acc[0][2] += av.x * bv.z; acc[0][3] += av.x * bv.w;
            acc[1][0] += av.y * bv.x; acc[1][1] += av.y * bv.y; acc[1][2] += av.y * bv.z; acc[1][3] += av.y * bv.w;
            acc[2][0] += av.z * bv.x; acc[2][1] += av.z * bv.y; acc[2][2] += av.z * bv.z; acc[2][3] += av.z * bv.w;
            acc[3][0] += av.w * bv.x; acc[3][1] += av.w * bv.y; acc[3][2] += av.w * bv.z; acc[3][3] += av.w * bv.w;
        }
    }

    if (OMODE == OM_PART) {
        float* cp = C + (size_t)blockIdx.z * (gridDim.y * 64) * N;
        #pragma unroll
        for (int i = 0; i < 4; i++) {
            int m = mbase + ty * 4 + i;
            #pragma unroll
            for (int j = 0; j < 4; j++) {
                int n = nbase + tx * 4 + j;
                if (n < N) cp[(size_t)m * N + n] = acc[i][j];
            }
        }
    } else if (OMODE == OM_PLAIN) {
        #pragma unroll
        for (int i = 0; i < 4; i++) {
            int m = mbase + ty * 4 + i;
            #pragma unroll
            for (int j = 0; j < 4; j++) {
                int n = nbase + tx * 4 + j;
                if (n < N) C[(size_t)m * N + n] = acc[i][j] + bias[n];
            }
        }
    } else { // OM_PRED: out[b][t][n] = (acc+bias)*mask
        #pragma unroll
        for (int i = 0; i < 4; i++) {
            int m = mbase + ty * 4 + i;
            float mf = (t < g_dlen[m]) ? 1.f : 0.f;
            #pragma unroll
            for (int j = 0; j < 4; j++) {
                int n = nbase + tx * 4 + j;
                if (n < N)
                    C[OFF_PRED + ((size_t)m * T + t) * VV + n] = (acc[i][j] + bias[n]) * mf;
            }
        }
    }
}

// ============================================================
// attention logits: a[b,p] = relu(enc_att[b,p,:] + dec[b,:]) . W_full + b_full
// one warp per (b,p)
// ============================================================
__global__ __launch_bounds__(256) void k_att(const float* __restrict__ bdec,
                                             const float* __restrict__ wfull,
                                             const float* __restrict__ bfull) {
    int gw = blockIdx.x * 8 + (threadIdx.x >> 5);   // (b*196+p), < 12544
    int lane = threadIdx.x & 31;
    int b = gw / P;
    const float* ea = g_encatt + (size_t)gw * AA;
    const float* d1 = g_part1 + (size_t)b * 7168;   // dec partial (cols 0..1023)
    float s = 0.f;
    #pragma unroll 8
    for (int a = lane; a < AA; a += 32) {
        float v = ea[a] + d1[a] + bdec[a];
        v = fmaxf(v, 0.f);
        s += v * wfull[a];
    }
    #pragma unroll
    for (int o = 16; o > 0; o >>= 1) s += __shfl_down_sync(0xffffffffu, s, o);
    if (lane == 0) g_alog[gw] = s + bfull[0];
}

// ============================================================
// softmax over P per batch row; write alpha and masked alpha to output
// ============================================================
__global__ void k_softmax(int t, float* __restrict__ out) {
    __shared__ float sv[P];
    __shared__ float red[256];
    int b = blockIdx.x, tid = threadIdx.x;
    float v = (tid < P) ? g_alog[b * P + tid] : -3.0e38f;
    if (tid < P) sv[tid] = v;
    red[tid] = v;
    __syncthreads();
    for (int o = 128; o > 0; o >>= 1) { if (tid < o) red[tid] = fmaxf(red[tid], red[tid + o]); __syncthreads(); }
    float mx = red[0];
    __syncthreads();
    float e = (tid < P) ? expf(sv[tid] - mx) : 0.f;
    red[tid] = e;
    __syncthreads();
    for (int o = 128; o > 0; o >>= 1) { if (tid < o) red[tid] += red[tid + o]; __syncthreads(); }
    float inv = 1.f / red[0];
    if (tid < P) {
        float al = e * inv;
        g_alpha[b * P + tid] = al;
        float mf = (t < g_dlen[b]) ? 1.f : 0.f;
        out[OFF_ALPHA + ((size_t)b * T + t) * P + tid] = al * mf;
    }
}

// ============================================================
// context + gate: awe[b,e] = sigmoid(beta[b,e]) * sum_p eo[b,p,e]*alpha[b,p]
// ============================================================
__global__ __launch_bounds__(256) void k_ctx(const float* __restrict__ enc_out,
                                             const float* __restrict__ bbeta) {
    __shared__ float al[P];
    int b = blockIdx.x >> 3, ch = blockIdx.x & 7;
    int tid = threadIdx.x;
    if (tid < P) al[tid] = g_alpha[b * P + tid];
    __syncthreads();
    int e = ch * 256 + tid;
    const float* src = enc_out + (size_t)g_ind[b] * P * ENC + e;
    float s = 0.f;
    #pragma unroll 4
    for (int p = 0; p < P; p++) s += src[(size_t)p * ENC] * al[p];
    float beta = g_part1[(size_t)b * 7168 + 1024 + e] + bbeta[e];
    g_awe[(size_t)b * ENC + e] = s * sigf(beta);
}

// ============================================================
// LSTM pointwise: sum ih partials + hh partial + biases -> gates -> h,c update
// ============================================================
__global__ void k_lstm(const float* __restrict__ bih, const float* __restrict__ bhh, int t) {
    int idx = blockIdx.x * 256 + threadIdx.x;   // < 65536
    int b = idx >> 10, j = idx & 1023;
    const float* p2a = g_part2 + (size_t)b * 4096;
    const float* p2b = g_part2 + (size_t)(B + b) * 4096;
    const float* p1h = g_part1 + (size_t)b * 7168 + 3072;
    float gi = p2a[j]        + p2b[j]        + bih[j]        + p1h[j]        + bhh[j];
    float gf = p2a[j + 1024] + p2b[j + 1024] + bih[j + 1024] + p1h[j + 1024] + bhh[j + 1024];
    float gg = p2a[j + 2048] + p2b[j + 2048] + bih[j + 2048] + p1h[j + 2048] + bhh[j + 2048];
    float go = p2a[j + 3072] + p2b[j + 3072] + bih[j + 3072] + p1h[j + 3072] + bhh[j + 3072];
    float c = g_c[idx];
    float cn = sigf(gf) * c + sigf(gi) * tanhf(gg);
    float hn = sigf(go) * tanhf(cn);
    if (t < g_dlen[b]) { g_c[idx] = cn; g_h[idx] = hn; }
}

// ============================================================
extern "C" void kernel_launch(void* const* d_in, const int* in_sizes, int n_in,
                              void* d_out, int out_size) {
    const float* enc_out   = (const float*)d_in[0];
    const int*   caps      = (const int*)  d_in[1];
    const int*   lengths   = (const int*)  d_in[2];
    const float* W_enc_att = (const float*)d_in[3];
    const float* b_enc_att = (const float*)d_in[4];
    const float* W_dec_att = (const float*)d_in[5];
    const float* b_dec_att = (const float*)d_in[6];
    const float* W_full    = (const float*)d_in[7];
    const float* b_full    = (const float*)d_in[8];
    const float* emb       = (const float*)d_in[9];
    const float* W_ih      = (const float*)d_in[10];
    const float* b_ih      = (const float*)d_in[11];
    const float* W_hh      = (const float*)d_in[12];
    const float* b_hh      = (const float*)d_in[13];
    const float* W_init_h  = (const float*)d_in[14];
    const float* b_init_h  = (const float*)d_in[15];
    const float* W_init_c  = (const float*)d_in[16];
    const float* b_init_c  = (const float*)d_in[17];
    const float* W_beta    = (const float*)d_in[18];
    const float* b_beta    = (const float*)d_in[19];
    const float* W_fc      = (const float*)d_in[20];
    const float* b_fc      = (const float*)d_in[21];
    float* out = (float*)d_out;

    float *p_mean, *p_h, *p_c, *p_encatt, *p_part1, *p_awe, *p_part2;
    cudaGetSymbolAddress((void**)&p_mean,   g_mean);
    cudaGetSymbolAddress((void**)&p_h,      g_h);
    cudaGetSymbolAddress((void**)&p_c,      g_c);
    cudaGetSymbolAddress((void**)&p_encatt, g_encatt);
    cudaGetSymbolAddress((void**)&p_part1,  g_part1);
    cudaGetSymbolAddress((void**)&p_awe,    g_awe);
    cudaGetSymbolAddress((void**)&p_part2,  g_part2);

    // ---- setup
    k_sort<<<1, 64>>>(lengths, caps, out);
    k_mean<<<512, 256>>>(enc_out);
    gemm64<AM_PLAIN, BM_PLAIN, OM_PLAIN><<<dim3(16, 1, 1), 256>>>(
        p_mean, ENC, nullptr, nullptr, nullptr, 0,
        W_init_h, nullptr, nullptr, b_init_h, p_h, H, ENC);
    gemm64<AM_PLAIN, BM_PLAIN, OM_PLAIN><<<dim3(16, 1, 1), 256>>>(
        p_mean, ENC, nullptr, nullptr, nullptr, 0,
        W_init_c, nullptr, nullptr, b_init_c, p_c, H, ENC);
    // enc_att = eo @ W_enc_att^T + b  (12544 x 1024, K=2048)
    gemm64<AM_ENC, BM_PLAIN, OM_PLAIN><<<dim3(16, 196, 1), 256>>>(
        nullptr, 0, enc_out, nullptr, nullptr, 0,
        W_enc_att, nullptr, nullptr, b_enc_att, p_encatt, AA, ENC);

    // ---- 31 sequential decode steps
    for (int t = 0; t < T; t++) {
        // fused [dec | beta | hh] = h @ [Wdec;Wbeta;Whh]^T  (N=7168, K=1024)
        gemm64<AM_PLAIN, BM_G1, OM_PART><<<dim3(112, 1, 1), 256>>>(
            p_h, H, nullptr, nullptr, nullptr, 0,
            W_dec_att, W_beta, W_hh, nullptr, p_part1, 7168, 1024);
        k_att<<<1568, 256>>>(b_dec_att, W_full, b_full);
        k_softmax<<<64, 256>>>(t, out);
        k_ctx<<<512, 256>>>(enc_out, b_beta);
        // gates_ih partials = [emb_t | awe] @ W_ih^T  (N=4096, K=2560, split-K=2)
        gemm64<AM_X, BM_PLAIN, OM_PART><<<dim3(64, 1, 2), 256>>>(
            nullptr, 0, nullptr, emb, p_awe, t,
            W_ih, nullptr, nullptr, nullptr, p_part2, 4096, 2560);
        k_lstm<<<256, 256>>>(b_ih, b_hh, t);
        // preds = h_new @ W_fc^T + b_fc, masked, straight to output
        gemm64<AM_PLAIN, BM_PLAIN, OM_PRED><<<dim3(157, 1, 1), 256>>>(
            p_h, H, nullptr, nullptr, nullptr, t,
            W_fc, nullptr, nullptr, b_fc, out, VV, H);
    }
    (void)in_sizes; (void)n_in; (void)out_size;
}

// round 3
// speedup vs baseline: 1.0071x; 1.0071x over previous
#include <cuda_runtime.h>

#define B   64
#define P   196
#define ENC 2048
#define H   1024
#define AA  1024
#define EE  512
#define VV  10000
#define TC  32
#define T   31

// ---- output layout: concat(predictions, alphas, caps, dec_lens, ind), float32
#define OFF_PRED  0ULL
#define OFF_ALPHA 19840000ULL
#define OFF_CAPS  20228864ULL
#define OFF_DLEN  20230912ULL
#define OFF_IND   20230976ULL

// ---- device scratch (static globals: allowed; no runtime allocation)
__device__ int   g_ind[B];
__device__ int   g_dlen[B];
__device__ int   g_caps[B * TC];
__device__ float g_mean[B * ENC];
__device__ float g_h[B * H];
__device__ float g_c[B * H];
__device__ float g_encatt[(size_t)B * P * AA];   // 51.4 MB
__device__ float g_part1[B * 7168];              // [dec | beta | hh] = h @ [Wdec;Wbeta;Whh]^T (no bias)
__device__ float g_alog[B * P];
__device__ float g_alpha[B * P];
__device__ float g_awe[B * ENC];
__device__ float g_part2[2 * B * 4096];          // split-K=2 partials of x @ W_ih^T

__device__ __forceinline__ float sigf(float x) { return 1.f / (1.f + expf(-x)); }

// ============================================================
// sort: stable argsort of -lengths; emit ind/dec_lens/caps tail of output
// ============================================================
__global__ void k_sort(const int* __restrict__ lengths,
                       const int* __restrict__ caps_in,
                       float* __restrict__ out) {
    int i = threadIdx.x;           // 0..63
    int li = lengths[i];
    int r = 0;
    for (int j = 0; j < B; j++) {
        int lj = lengths[j];
        if (lj > li || (lj == li && j < i)) r++;
    }
    g_ind[r]  = i;
    g_dlen[r] = li - 1;
    out[OFF_DLEN + r] = (float)(li - 1);
    out[OFF_IND + r]  = (float)i;
    for (int t = 0; t < TC; t++) {
        int cv = caps_in[i * TC + t];
        g_caps[r * TC + t] = cv;
        out[OFF_CAPS + (size_t)r * TC + t] = (float)cv;
    }
}

// ============================================================
// mean over P of sorted enc_out
// ============================================================
__global__ __launch_bounds__(256) void k_mean(const float* __restrict__ enc_out) {
    int b = blockIdx.x >> 3, ch = blockIdx.x & 7;
    int e = ch * 256 + threadIdx.x;
    const float* src = enc_out + (size_t)g_ind[b] * P * ENC + e;
    float s = 0.f;
    #pragma unroll 4
    for (int p = 0; p < P; p++) s += src[(size_t)p * ENC];
    g_mean[(size_t)b * ENC + e] = s * (1.f / 196.f);
}

// ============================================================
// generic 64xN tiled fp32 GEMM:  C[M,N] = A[M,K] @ W[N,K]^T (+bias)
// block tile 64x64, KT=32, 256 threads, 4x4 microtile
// ============================================================
enum { AM_PLAIN = 0, AM_ENC = 1, AM_X = 2 };   // A source
enum { BM_PLAIN = 0, BM_G1 = 2 };              // W source
enum { OM_PART = 0, OM_PLAIN = 1, OM_PRED = 2 };

template <int AMODE, int BMODE, int OMODE>
__global__ __launch_bounds__(256) void gemm64(
    const float* __restrict__ A, int lda,
    const float* __restrict__ encsrc,
    const float* __restrict__ embp, const float* __restrict__ awep, int t,
    const float* __restrict__ W0, const float* __restrict__ W1, const float* __restrict__ W2,
    const float* __restrict__ bias,
    float* __restrict__ C, int N, int K)
{
    __shared__ float As[32][64];
    __shared__ float Bs[32][64];
    __shared__ int   srow[64];

    const int tid = threadIdx.x;
    const int tx = tid & 15, ty = tid >> 4;
    const int nbase = blockIdx.x * 64;
    const int mbase = blockIdx.y * 64;
    const int S = gridDim.z;
    const int kLen = K / S;
    const int kStart = blockIdx.z * kLen;

    if (AMODE == AM_ENC) {
        if (tid < 64) { int m = mbase + tid; srow[tid] = g_ind[m / 196] * 196 + (m % 196); }
        __syncthreads();
    } else if (AMODE == AM_X) {
        if (tid < 64) srow[tid] = g_caps[(mbase + tid) * TC + t];
        __syncthreads();
    }

    float acc[4][4];
    #pragma unroll
    for (int i = 0; i < 4; i++)
        #pragma unroll
        for (int j = 0; j < 4; j++) acc[i][j] = 0.f;

    const int la = tid >> 2;          // 0..63: row within tile that this thread loads
    const int lk = (tid & 3) * 8;     // k offset: 0,8,16,24

    for (int k0 = kStart; k0 < kStart + kLen; k0 += 32) {
        // ---- fetch A fragment (row mbase+la, k = k0+lk .. +7)
        float4 a0, a1;
        {
            int kg = k0 + lk;
            if (AMODE == AM_PLAIN) {
                const float* p = A + (size_t)(mbase + la) * lda + kg;
                a0 = *(const float4*)p; a1 = *(const float4*)(p + 4);
            } else if (AMODE == AM_ENC) {
                const float* p = encsrc + (size_t)srow[la] * ENC + kg;
                a0 = *(const float4*)p; a1 = *(const float4*)(p + 4);
            } else { // AM_X: [emb_t | awe]
                const float* p0 = (kg < EE) ? (embp + (size_t)srow[la] * EE + kg)
                                            : (awep + (size_t)(mbase + la) * ENC + (kg - EE));
                a0 = *(const float4*)p0;
                int kg1 = kg + 4;
                const float* p1 = (kg1 < EE) ? (embp + (size_t)srow[la] * EE + kg1)
                                             : (awep + (size_t)(mbase + la) * ENC + (kg1 - EE));
                a1 = *(const float4*)p1;
            }
        }
        // ---- fetch W fragment (row nbase+la, k = k0+lk .. +7)
        float4 b0, b1;
        {
            int n = nbase + la;
            int kg = k0 + lk;
            const float* wp = nullptr;
            if (BMODE == BM_PLAIN) {
                if (n < N) wp = W0 + (size_t)n * K + kg;
            } else { // BM_G1: rows [0,1024)=Wdec, [1024,3072)=Wbeta, [3072,7168)=Whh, all K=1024
                if (n < 1024)      wp = W0 + (size_t)n * 1024 + kg;
                else if (n < 3072) wp = W1 + (size_t)(n - 1024) * 1024 + kg;
                else               wp = W2 + (size_t)(n - 3072) * 1024 + kg;
            }
            if (wp) { b0 = *(const float4*)wp; b1 = *(const float4*)(wp + 4); }
            else    { b0 = make_float4(0.f, 0.f, 0.f, 0.f); b1 = b0; }
        }
        __syncthreads();   // protect previous iteration's reads
        As[lk + 0][la] = a0.x; As[lk + 1][la] = a0.y; As[lk + 2][la] = a0.z; As[lk + 3][la] = a0.w;
        As[lk + 4][la] = a1.x; As[lk + 5][la] = a1.y; As[lk + 6][la] = a1.z; As[lk + 7][la] = a1.w;
        Bs[lk + 0][la] = b0.x; Bs[lk + 1][la] = b0.y; Bs[lk + 2][la] = b0.z; Bs[lk + 3][la] = b0.w;
        Bs[lk + 4][la] = b1.x; Bs[lk + 5][la] = b1.y; Bs[lk + 6][la] = b1.z; Bs[lk + 7][la] = b1.w;
        __syncthreads();
        #pragma unroll
        for (int kk = 0; kk < 32; kk++) {
            float4 av = *(const float4*)&As[kk][ty * 4];
            float4 bv = *(const float4*)&Bs[kk][tx * 4];
            acc[0][0] += av.x * bv.x; acc[0][1] += av.x * bv.y; acc[0][2] += av.x * bv.z; acc[0][3] += av.x * bv.w;
            acc[1][0] += av.y * bv.x; acc[1][1] += av.y * bv.y; acc[1][2] += av.y * bv.z; acc[1][3] += av.y * bv.w;
            acc[2][0] += av.z * bv.x; acc[2][1] += av.z * bv.y; acc[2][2] += av.z * bv.z; acc[2][3] += av.z * bv.w;
            acc[3][0] += av.w * bv.x; acc[3][1] += av.w * bv.y; acc[3][2] += av.w * bv.z; acc[3][3] += av.w * bv.w;
        }
    }

    if (OMODE == OM_PART) {
        float* cp = C + (size_t)blockIdx.z * (gridDim.y * 64) * N;
        #pragma unroll
        for (int i = 0; i < 4; i++) {
            int m = mbase + ty * 4 + i;
            #pragma unroll
            for (int j = 0; j < 4; j++) {
                int n = nbase + tx * 4 + j;
                if (n < N) cp[(size_t)m * N + n] = acc[i][j];
            }
        }
    } else if (OMODE == OM_PLAIN) {
        #pragma unroll
        for (int i = 0; i < 4; i++) {
            int m = mbase + ty * 4 + i;
            #pragma unroll
            for (int j = 0; j < 4; j++) {
                int n = nbase + tx * 4 + j;
                if (n < N) C[(size_t)m * N + n] = acc[i][j] + bias[n];
            }
        }
    } else { // OM_PRED: out[b][t][n] = (acc+bias)*mask
        #pragma unroll
        for (int i = 0; i < 4; i++) {
            int m = mbase + ty * 4 + i;
            float mf = (t < g_dlen[m]) ? 1.f : 0.f;
            #pragma unroll
            for (int j = 0; j < 4; j++) {
                int n = nbase + tx * 4 + j;
                if (n < N)
                    C[OFF_PRED + ((size_t)m * T + t) * VV + n] = (acc[i][j] + bias[n]) * mf;
            }
        }
    }
}

// ============================================================
// attention logits: a[b,p] = relu(enc_att[b,p,:] + dec[b,:]) . W_full + b_full
// one warp per (b,p)
// ============================================================
__global__ __launch_bounds__(256) void k_att(const float* __restrict__ bdec,
                                             const float* __restrict__ wfull,
                                             const float* __restrict__ bfull) {
    int gw = blockIdx.x * 8 + (threadIdx.x >> 5);   // (b*196+p), < 12544
    int lane = threadIdx.x & 31;
    int b = gw / P;
    const float* ea = g_encatt + (size_t)gw * AA;
    const float* d1 = g_part1 + (size_t)b * 7168;   // dec partial (cols 0..1023)
    float s = 0.f;
    #pragma unroll 8
    for (int a = lane; a < AA; a += 32) {
        float v = ea[a] + d1[a] + bdec[a];
        v = fmaxf(v, 0.f);
        s += v * wfull[a];
    }
    #pragma unroll
    for (int o = 16; o > 0; o >>= 1) s += __shfl_down_sync(0xffffffffu, s, o);
    if (lane == 0) g_alog[gw] = s + bfull[0];
}

// ============================================================
// softmax over P per batch row; write alpha and masked alpha to output
// ============================================================
__global__ void k_softmax(int t, float* __restrict__ out) {
    __shared__ float sv[P];
    __shared__ float red[256];
    int b = blockIdx.x, tid = threadIdx.x;
    float v = (tid < P) ? g_alog[b * P + tid] : -3.0e38f;
    if (tid < P) sv[tid] = v;
    red[tid] = v;
    __syncthreads();
    for (int o = 128; o > 0; o >>= 1) { if (tid < o) red[tid] = fmaxf(red[tid], red[tid + o]); __syncthreads(); }
    float mx = red[0];
    __syncthreads();
    float e = (tid < P) ? expf(sv[tid] - mx) : 0.f;
    red[tid] = e;
    __syncthreads();
    for (int o = 128; o > 0; o >>= 1) { if (tid < o) red[tid] += red[tid + o]; __syncthreads(); }
    float inv = 1.f / red[0];
    if (tid < P) {
        float al = e * inv;
        g_alpha[b * P + tid] = al;
        float mf = (t < g_dlen[b]) ? 1.f : 0.f;
        out[OFF_ALPHA + ((size_t)b * T + t) * P + tid] = al * mf;
    }
}

// ============================================================
// context + gate: awe[b,e] = sigmoid(beta[b,e]) * sum_p eo[b,p,e]*alpha[b,p]
// ============================================================
__global__ __launch_bounds__(256) void k_ctx(const float* __restrict__ enc_out,
                                             const float* __restrict__ bbeta) {
    __shared__ float al[P];
    int b = blockIdx.x >> 3, ch = blockIdx.x & 7;
    int tid = threadIdx.x;
    if (tid < P) al[tid] = g_alpha[b * P + tid];
    __syncthreads();
    int e = ch * 256 + tid;
    const float* src = enc_out + (size_t)g_ind[b] * P * ENC + e;
    float s = 0.f;
    #pragma unroll 4
    for (int p = 0; p < P; p++) s += src[(size_t)p * ENC] * al[p];
    float beta = g_part1[(size_t)b * 7168 + 1024 + e] + bbeta[e];
    g_awe[(size_t)b * ENC + e] = s * sigf(beta);
}

// ============================================================
// LSTM pointwise: sum ih partials + hh partial + biases -> gates -> h,c update
// ============================================================
__global__ void k_lstm(const float* __restrict__ bih, const float* __restrict__ bhh, int t) {
    int idx = blockIdx.x * 256 + threadIdx.x;   // < 65536
    int b = idx >> 10, j = idx & 1023;
    const float* p2a = g_part2 + (size_t)b * 4096;
    const float* p2b = g_part2 + (size_t)(B + b) * 4096;
    const float* p1h = g_part1 + (size_t)b * 7168 + 3072;
    float gi = p2a[j]        + p2b[j]        + bih[j]        + p1h[j]        + bhh[j];
    float gf = p2a[j + 1024] + p2b[j + 1024] + bih[j + 1024] + p1h[j + 1024] + bhh[j + 1024];
    float gg = p2a[j + 2048] + p2b[j + 2048] + bih[j + 2048] + p1h[j + 2048] + bhh[j + 2048];
    float go = p2a[j + 3072] + p2b[j + 3072] + bih[j + 3072] + p1h[j + 3072] + bhh[j + 3072];
    float c = g_c[idx];
    float cn = sigf(gf) * c + sigf(gi) * tanhf(gg);
    float hn = sigf(go) * tanhf(cn);
    if (t < g_dlen[b]) { g_c[idx] = cn; g_h[idx] = hn; }
}

// ============================================================
extern "C" void kernel_launch(void* const* d_in, const int* in_sizes, int n_in,
                              void* d_out, int out_size) {
    const float* enc_out   = (const float*)d_in[0];
    const int*   caps      = (const int*)  d_in[1];
    const int*   lengths   = (const int*)  d_in[2];
    const float* W_enc_att = (const float*)d_in[3];
    const float* b_enc_att = (const float*)d_in[4];
    const float* W_dec_att = (const float*)d_in[5];
    const float* b_dec_att = (const float*)d_in[6];
    const float* W_full    = (const float*)d_in[7];
    const float* b_full    = (const float*)d_in[8];
    const float* emb       = (const float*)d_in[9];
    const float* W_ih      = (const float*)d_in[10];
    const float* b_ih      = (const float*)d_in[11];
    const float* W_hh      = (const float*)d_in[12];
    const float* b_hh      = (const float*)d_in[13];
    const float* W_init_h  = (const float*)d_in[14];
    const float* b_init_h  = (const float*)d_in[15];
    const float* W_init_c  = (const float*)d_in[16];
    const float* b_init_c  = (const float*)d_in[17];
    const float* W_beta    = (const float*)d_in[18];
    const float* b_beta    = (const float*)d_in[19];
    const float* W_fc      = (const float*)d_in[20];
    const float* b_fc      = (const float*)d_in[21];
    float* out = (float*)d_out;

    float *p_mean, *p_h, *p_c, *p_encatt, *p_part1, *p_awe, *p_part2;
    cudaGetSymbolAddress((void**)&p_mean,   g_mean);
    cudaGetSymbolAddress((void**)&p_h,      g_h);
    cudaGetSymbolAddress((void**)&p_c,      g_c);
    cudaGetSymbolAddress((void**)&p_encatt, g_encatt);
    cudaGetSymbolAddress((void**)&p_part1,  g_part1);
    cudaGetSymbolAddress((void**)&p_awe,    g_awe);
    cudaGetSymbolAddress((void**)&p_part2,  g_part2);

    // ---- setup
    k_sort<<<1, 64>>>(lengths, caps, out);
    k_mean<<<512, 256>>>(enc_out);
    gemm64<AM_PLAIN, BM_PLAIN, OM_PLAIN><<<dim3(16, 1, 1), 256>>>(
        p_mean, ENC, nullptr, nullptr, nullptr, 0,
        W_init_h, nullptr, nullptr, b_init_h, p_h, H, ENC);
    gemm64<AM_PLAIN, BM_PLAIN, OM_PLAIN><<<dim3(16, 1, 1), 256>>>(
        p_mean, ENC, nullptr, nullptr, nullptr, 0,
        W_init_c, nullptr, nullptr, b_init_c, p_c, H, ENC);
    // enc_att = eo @ W_enc_att^T + b  (12544 x 1024, K=2048)
    gemm64<AM_ENC, BM_PLAIN, OM_PLAIN><<<dim3(16, 196, 1), 256>>>(
        nullptr, 0, enc_out, nullptr, nullptr, 0,
        W_enc_att, nullptr, nullptr, b_enc_att, p_encatt, AA, ENC);

    // ---- 31 sequential decode steps
    for (int t = 0; t < T; t++) {
        // fused [dec | beta | hh] = h @ [Wdec;Wbeta;Whh]^T  (N=7168, K=1024)
        gemm64<AM_PLAIN, BM_G1, OM_PART><<<dim3(112, 1, 1), 256>>>(
            p_h, H, nullptr, nullptr, nullptr, 0,
            W_dec_att, W_beta, W_hh, nullptr, p_part1, 7168, 1024);
        k_att<<<1568, 256>>>(b_dec_att, W_full, b_full);
        k_softmax<<<64, 256>>>(t, out);
        k_ctx<<<512, 256>>>(enc_out, b_beta);
        // gates_ih partials = [emb_t | awe] @ W_ih^T  (N=4096, K=2560, split-K=2)
        gemm64<AM_X, BM_PLAIN, OM_PART><<<dim3(64, 1, 2), 256>>>(
            nullptr, 0, nullptr, emb, p_awe, t,
            W_ih, nullptr, nullptr, nullptr, p_part2, 4096, 2560);
        k_lstm<<<256, 256>>>(b_ih, b_hh, t);
        // preds = h_new @ W_fc^T + b_fc, masked, straight to output
        gemm64<AM_PLAIN, BM_PLAIN, OM_PRED><<<dim3(157, 1, 1), 256>>>(
            p_h, H, nullptr, nullptr, nullptr, t,
            W_fc, nullptr, nullptr, b_fc, out, VV, H);
    }
    (void)in_sizes; (void)n_in; (void)out_size;
}

// round 4
// speedup vs baseline: 1.3423x; 1.3328x over previous
#include <cuda_runtime.h>

#define B   64
#define P   196
#define ENC 2048
#define H   1024
#define AA  1024
#define EE  512
#define VV  10000
#define TC  32
#define T   31
#define MT  (T * B)          // 1984 rows of h-history / emb-gates

// ---- output layout: concat(predictions, alphas, caps, dec_lens, ind), float32
#define OFF_PRED  0ULL
#define OFF_ALPHA 19840000ULL
#define OFF_CAPS  20228864ULL
#define OFF_DLEN  20230912ULL
#define OFF_IND   20230976ULL

// ---- device scratch
__device__ int   g_ind[B];
__device__ int   g_dlen[B];
__device__ int   g_caps[B * TC];
__device__ float g_mean[B * ENC];
__device__ float g_h[B * H];
__device__ float g_c[B * H];
__device__ float g_encatt[(size_t)B * P * AA];    // 51.4 MB
__device__ float g_part1[2 * B * 7168];           // split-K=2 partials of h @ [Wdec;Wbeta;Whh]^T
__device__ float g_alog[B * P];
__device__ float g_awe[B * ENC];
__device__ float g_part2[2 * B * 4096];           // split-K=2 partials of awe @ W_ih[:,512:]^T
__device__ float g_embg[(size_t)MT * 4096];       // precomputed emb @ W_ih[:,:512]^T   (32.5 MB)
__device__ float g_hhist[(size_t)MT * H];         // h_new history for batched fc GEMM  (8.1 MB)

__device__ __forceinline__ float sigf(float x) { return 1.f / (1.f + expf(-x)); }

// ============================================================
// stable argsort of -lengths; emit ind/dec_lens/caps tail of output
// ============================================================
__global__ void k_sort(const int* __restrict__ lengths,
                       const int* __restrict__ caps_in,
                       float* __restrict__ out) {
    int i = threadIdx.x;           // 0..63
    int li = lengths[i];
    int r = 0;
    for (int j = 0; j < B; j++) {
        int lj = lengths[j];
        if (lj > li || (lj == li && j < i)) r++;
    }
    g_ind[r]  = i;
    g_dlen[r] = li - 1;
    out[OFF_DLEN + r] = (float)(li - 1);
    out[OFF_IND + r]  = (float)i;
    for (int t = 0; t < TC; t++) {
        int cv = caps_in[i * TC + t];
        g_caps[r * TC + t] = cv;
        out[OFF_CAPS + (size_t)r * TC + t] = (float)cv;
    }
}

// ============================================================
// mean over P of sorted enc_out
// ============================================================
__global__ __launch_bounds__(256) void k_mean(const float* __restrict__ enc_out) {
    int b = blockIdx.x >> 3, ch = blockIdx.x & 7;
    int e = ch * 256 + threadIdx.x;
    const float* src = enc_out + (size_t)g_ind[b] * P * ENC + e;
    float s = 0.f;
    #pragma unroll 4
    for (int p = 0; p < P; p++) s += src[(size_t)p * ENC];
    g_mean[(size_t)b * ENC + e] = s * (1.f / 196.f);
}

// ============================================================
// 64xN tiled fp32 GEMM with register prefetch + optional split-K
// C[M,N] = A[M,K] @ W[N,K]^T (+bias); tile 64x64, KT=32, 256 thr, 4x4 micro
// ============================================================
enum { AM_PLAIN = 0, AM_ENC = 1, AM_EMB = 2 };   // A source
enum { BM_PLAIN = 0, BM_G1 = 1 };                // W source
enum { OM_PART = 0, OM_PLAIN = 1, OM_PRED = 2 };

template <int AMODE, int BMODE, int OMODE>
__global__ __launch_bounds__(256) void gemm64(
    const float* __restrict__ A, int lda,
    const float* __restrict__ W0, const float* __restrict__ W1, const float* __restrict__ W2,
    int ldw, int wofs,
    const float* __restrict__ bias,
    float* __restrict__ C, int N, int K)
{
    __shared__ float As[32][64];
    __shared__ float Bs[32][64];
    __shared__ int   srow[64];

    const int tid = threadIdx.x;
    const int tx = tid & 15, ty = tid >> 4;
    const int nbase = blockIdx.x * 64;
    const int mbase = blockIdx.y * 64;
    const int kLen = K / gridDim.z;
    const int kStart = blockIdx.z * kLen;
    const int la = tid >> 2;          // 0..63: row loaded by this thread
    const int lk = (tid & 3) * 8;     // k offset 0/8/16/24

    if (AMODE == AM_ENC) {
        if (tid < 64) { int m = mbase + tid; srow[tid] = g_ind[m / 196] * 196 + (m % 196); }
        __syncthreads();
    } else if (AMODE == AM_EMB) {
        if (tid < 64) srow[tid] = g_caps[tid * TC + (mbase >> 6)];
        __syncthreads();
    }

    const float* pA;
    if (AMODE == AM_PLAIN) pA = A + (size_t)(mbase + la) * lda + kStart + lk;
    else                   pA = A + (size_t)srow[la] * lda + kStart + lk;

    const float* pB = nullptr;
    {
        int n = nbase + la;
        if (BMODE == BM_PLAIN) {
            if (n < N) pB = W0 + (size_t)n * ldw + wofs + kStart + lk;
        } else {   // G1: rows [0,1024)=Wdec, [1024,3072)=Wbeta, [3072,7168)=Whh, K=1024
            if (n < 1024)      pB = W0 + (size_t)n * 1024 + kStart + lk;
            else if (n < 3072) pB = W1 + (size_t)(n - 1024) * 1024 + kStart + lk;
            else               pB = W2 + (size_t)(n - 3072) * 1024 + kStart + lk;
        }
    }

    // prologue prefetch of first tile
    float4 a0 = *(const float4*)pA, a1 = *(const float4*)(pA + 4);
    float4 b0, b1;
    if (pB) { b0 = *(const float4*)pB; b1 = *(const float4*)(pB + 4); }
    else    { b0 = make_float4(0.f, 0.f, 0.f, 0.f); b1 = b0; }

    float acc[4][4];
    #pragma unroll
    for (int i = 0; i < 4; i++)
        #pragma unroll
        for (int j = 0; j < 4; j++) acc[i][j] = 0.f;

    const int nTiles = kLen >> 5;
    for (int it = 0; it < nTiles; it++) {
        __syncthreads();   // smem free from previous compute
        As[lk + 0][la] = a0.x; As[lk + 1][la] = a0.y; As[lk + 2][la] = a0.z; As[lk + 3][la] = a0.w;
        As[lk + 4][la] = a1.x; As[lk + 5][la] = a1.y; As[lk + 6][la] = a1.z; As[lk + 7][la] = a1.w;
        Bs[lk + 0][la] = b0.x; Bs[lk + 1][la] = b0.y; Bs[lk + 2][la] = b0.z; Bs[lk + 3][la] = b0.w;
        Bs[lk + 4][la] = b1.x; Bs[lk + 5][la] = b1.y; Bs[lk + 6][la] = b1.z; Bs[lk + 7][la] = b1.w;
        __syncthreads();
        if (it + 1 < nTiles) {   // issue next tile's loads; latency overlaps compute below
            pA += 32;
            a0 = *(const float4*)pA; a1 = *(const float4*)(pA + 4);
            if (pB) { pB += 32; b0 = *(const float4*)pB; b1 = *(const float4*)(pB + 4); }
        }
        #pragma unroll
        for (int kk = 0; kk < 32; kk++) {
            float4 av = *(const float4*)&As[kk][ty * 4];
            float4 bv = *(const float4*)&Bs[kk][tx * 4];
            acc[0][0] += av.x * bv.x; acc[0][1] += av.x * bv.y; acc[0][2] += av.x * bv.z; acc[0][3] += av.x * bv.w;
            acc[1][0] += av.y * bv.x; acc[1][1] += av.y * bv.y; acc[1][2] += av.y * bv.z; acc[1][3] += av.y * bv.w;
            acc[2][0] += av.z * bv.x; acc[2][1] += av.z * bv.y; acc[2][2] += av.z * bv.z; acc[2][3] += av.z * bv.w;
            acc[3][0] += av.w * bv.x; acc[3][1] += av.w * bv.y; acc[3][2] += av.w * bv.z; acc[3][3] += av.w * bv.w;
        }
    }

    if (OMODE == OM_PART) {
        #pragma unroll
        for (int i = 0; i < 4; i++) {
            int m = mbase + ty * 4 + i;
            size_t rowo = ((size_t)blockIdx.z * (gridDim.y * 64) + m) * N;
            #pragma unroll
            for (int j = 0; j < 4; j++) {
                int n = nbase + tx * 4 + j;
                if (n < N) C[rowo + n] = acc[i][j];
            }
        }
    } else if (OMODE == OM_PLAIN) {
        #pragma unroll
        for (int i = 0; i < 4; i++) {
            int m = mbase + ty * 4 + i;
            #pragma unroll
            for (int j = 0; j < 4; j++) {
                int n = nbase + tx * 4 + j;
                if (n < N) C[(size_t)m * N + n] = acc[i][j] + bias[n];
            }
        }
    } else {  // OM_PRED: row m = t*64+b -> out[b][t][n] = (acc+bias)*mask
        #pragma unroll
        for (int i = 0; i < 4; i++) {
            int m = mbase + ty * 4 + i;
            int tt = m >> 6, b = m & 63;
            float mf = (tt < g_dlen[b]) ? 1.f : 0.f;
            size_t oo = OFF_PRED + ((size_t)b * T + tt) * VV;
            #pragma unroll
            for (int j = 0; j < 4; j++) {
                int n = nbase + tx * 4 + j;
                if (n < N) C[oo + n] = (acc[i][j] + bias[n]) * mf;
            }
        }
    }
}

// ============================================================
// attention logits: a[b,p] = relu(enc_att[b,p,:] + dec[b,:]) . W_full
// (b_full dropped: softmax is shift-invariant). one warp per (b,p)
// ============================================================
__global__ __launch_bounds__(256) void k_att(const float* __restrict__ bdec,
                                             const float* __restrict__ wfull) {
    int gw = blockIdx.x * 8 + (threadIdx.x >> 5);   // (b*196+p) < 12544
    int lane = threadIdx.x & 31;
    int b = gw / P;
    const float* ea = g_encatt + (size_t)gw * AA;
    const float* d0 = g_part1 + (size_t)b * 7168;
    const float* d1 = g_part1 + (size_t)(B + b) * 7168;   // second split-K partial
    float s = 0.f;
    #pragma unroll 8
    for (int a = lane; a < AA; a += 32) {
        float v = ea[a] + d0[a] + d1[a] + bdec[a];
        v = fmaxf(v, 0.f);
        s += v * wfull[a];
    }
    #pragma unroll
    for (int o = 16; o > 0; o >>= 1) s += __shfl_down_sync(0xffffffffu, s, o);
    if (lane == 0) g_alog[gw] = s;
}

// ============================================================
// fused softmax + context + gate:
//   alpha = softmax_p(alog);  awe[b,e] = sigmoid(beta[b,e]) * sum_p eo[b,p,e]*alpha[p]
//   ch==0 block also writes masked alpha to output
// ============================================================
__global__ __launch_bounds__(256) void k_ctx(const float* __restrict__ enc_out,
                                             const float* __restrict__ bbeta,
                                             int t, float* __restrict__ out) {
    __shared__ float al[P];
    __shared__ float red[256];
    int b = blockIdx.x >> 3, ch = blockIdx.x & 7;
    int tid = threadIdx.x;
    float v = (tid < P) ? g_alog[b * P + tid] : -3.0e38f;
    red[tid] = v;
    __syncthreads();
    for (int o = 128; o > 0; o >>= 1) { if (tid < o) red[tid] = fmaxf(red[tid], red[tid + o]); __syncthreads(); }
    float mx = red[0];
    __syncthreads();
    float e0 = (tid < P) ? expf(v - mx) : 0.f;
    red[tid] = e0;
    __syncthreads();
    for (int o = 128; o > 0; o >>= 1) { if (tid < o) red[tid] += red[tid + o]; __syncthreads(); }
    float inv = 1.f / red[0];
    if (tid < P) {
        float a = e0 * inv;
        al[tid] = a;
        if (ch == 0) {
            float mf = (t < g_dlen[b]) ? 1.f : 0.f;
            out[OFF_ALPHA + ((size_t)b * T + t) * P + tid] = a * mf;
        }
    }
    __syncthreads();
    int e = ch * 256 + tid;
    const float* src = enc_out + (size_t)g_ind[b] * P * ENC + e;
    float s = 0.f;
    #pragma unroll 4
    for (int p = 0; p < P; p++) s += src[(size_t)p * ENC] * al[p];
    float beta = g_part1[(size_t)b * 7168 + 1024 + e]
               + g_part1[(size_t)(B + b) * 7168 + 1024 + e] + bbeta[e];
    g_awe[(size_t)b * ENC + e] = s * sigf(beta);
}

// ============================================================
// LSTM pointwise: embg + ih partials + hh partials + biases -> gates -> h,c
// also records h_new into g_hhist for the batched fc GEMM
// ============================================================
__global__ void k_lstm(const float* __restrict__ bih, const float* __restrict__ bhh, int t) {
    int idx = blockIdx.x * 256 + threadIdx.x;   // < 65536
    int b = idx >> 10, j = idx & 1023;
    const float* pe  = g_embg + ((size_t)t * B + b) * 4096;
    const float* p2a = g_part2 + (size_t)b * 4096;
    const float* p2b = g_part2 + (size_t)(B + b) * 4096;
    const float* h0  = g_part1 + (size_t)b * 7168 + 3072;
    const float* h1  = g_part1 + (size_t)(B + b) * 7168 + 3072;
    float gi = pe[j]        + p2a[j]        + p2b[j]        + bih[j]        + h0[j]        + h1[j]        + bhh[j];
    float gf = pe[j + 1024] + p2a[j + 1024] + p2b[j + 1024] + bih[j + 1024] + h0[j + 1024] + h1[j + 1024] + bhh[j + 1024];
    float gg = pe[j + 2048] + p2a[j + 2048] + p2b[j + 2048] + bih[j + 2048] + h0[j + 2048] + h1[j + 2048] + bhh[j + 2048];
    float go = pe[j + 3072] + p2a[j + 3072] + p2b[j + 3072] + bih[j + 3072] + h0[j + 3072] + h1[j + 3072] + bhh[j + 3072];
    float c = g_c[idx];
    float cn = sigf(gf) * c + sigf(gi) * tanhf(gg);
    float hn = sigf(go) * tanhf(cn);
    g_hhist[((size_t)t * B + b) * H + j] = hn;
    if (t < g_dlen[b]) { g_c[idx] = cn; g_h[idx] = hn; }
}

// ============================================================
extern "C" void kernel_launch(void* const* d_in, const int* in_sizes, int n_in,
                              void* d_out, int out_size) {
    const float* enc_out   = (const float*)d_in[0];
    const int*   caps      = (const int*)  d_in[1];
    const int*   lengths   = (const int*)  d_in[2];
    const float* W_enc_att = (const float*)d_in[3];
    const float* b_enc_att = (const float*)d_in[4];
    const float* W_dec_att = (const float*)d_in[5];
    const float* b_dec_att = (const float*)d_in[6];
    const float* W_full    = (const float*)d_in[7];
    // d_in[8] = b_full (unused: softmax shift-invariant)
    const float* emb       = (const float*)d_in[9];
    const float* W_ih      = (const float*)d_in[10];
    const float* b_ih      = (const float*)d_in[11];
    const float* W_hh      = (const float*)d_in[12];
    const float* b_hh      = (const float*)d_in[13];
    const float* W_init_h  = (const float*)d_in[14];
    const float* b_init_h  = (const float*)d_in[15];
    const float* W_init_c  = (const float*)d_in[16];
    const float* b_init_c  = (const float*)d_in[17];
    const float* W_beta    = (const float*)d_in[18];
    const float* b_beta    = (const float*)d_in[19];
    const float* W_fc      = (const float*)d_in[20];
    const float* b_fc      = (const float*)d_in[21];
    float* out = (float*)d_out;

    float *p_mean, *p_h, *p_c, *p_encatt, *p_part1, *p_awe, *p_part2, *p_embg, *p_hhist;
    cudaGetSymbolAddress((void**)&p_mean,   g_mean);
    cudaGetSymbolAddress((void**)&p_h,      g_h);
    cudaGetSymbolAddress((void**)&p_c,      g_c);
    cudaGetSymbolAddress((void**)&p_encatt, g_encatt);
    cudaGetSymbolAddress((void**)&p_part1,  g_part1);
    cudaGetSymbolAddress((void**)&p_awe,    g_awe);
    cudaGetSymbolAddress((void**)&p_part2,  g_part2);
    cudaGetSymbolAddress((void**)&p_embg,   g_embg);
    cudaGetSymbolAddress((void**)&p_hhist,  g_hhist);

    // ---- setup
    k_sort<<<1, 64>>>(lengths, caps, out);
    k_mean<<<512, 256>>>(enc_out);
    gemm64<AM_PLAIN, BM_PLAIN, OM_PLAIN><<<dim3(16, 1, 1), 256>>>(
        p_mean, ENC, W_init_h, nullptr, nullptr, ENC, 0, b_init_h, p_h, H, ENC);
    gemm64<AM_PLAIN, BM_PLAIN, OM_PLAIN><<<dim3(16, 1, 1), 256>>>(
        p_mean, ENC, W_init_c, nullptr, nullptr, ENC, 0, b_init_c, p_c, H, ENC);
    // enc_att = eo_sorted @ W_enc_att^T + b   (12544 x 1024, K=2048)
    gemm64<AM_ENC, BM_PLAIN, OM_PLAIN><<<dim3(16, 196, 1), 256>>>(
        enc_out, ENC, W_enc_att, nullptr, nullptr, ENC, 0, b_enc_att, p_encatt, AA, ENC);
    // precompute emb-part of LSTM input gates: (1984 x 4096, K=512)
    gemm64<AM_EMB, BM_PLAIN, OM_PART><<<dim3(64, T, 1), 256>>>(
        emb, EE, W_ih, nullptr, nullptr, 2560, 0, nullptr, p_embg, 4096, EE);

    // ---- 31 sequential decode steps
    for (int t = 0; t < T; t++) {
        // fused [dec | beta | hh] = h @ [Wdec;Wbeta;Whh]^T  (N=7168, K=1024, split-K=2)
        gemm64<AM_PLAIN, BM_G1, OM_PART><<<dim3(112, 1, 2), 256>>>(
            p_h, H, W_dec_att, W_beta, W_hh, 1024, 0, nullptr, p_part1, 7168, 1024);
        k_att<<<1568, 256>>>(b_dec_att, W_full);
        k_ctx<<<512, 256>>>(enc_out, b_beta, t, out);
        // awe-part of gates: awe @ W_ih[:,512:]^T  (N=4096, K=2048, split-K=2)
        gemm64<AM_PLAIN, BM_PLAIN, OM_PART><<<dim3(64, 1, 2), 256>>>(
            p_awe, ENC, W_ih, nullptr, nullptr, 2560, 512, nullptr, p_part2, 4096, 2048);
        k_lstm<<<256, 256>>>(b_ih, b_hh, t);
    }

    // ---- batched predictions: h_hist @ W_fc^T + b_fc, masked (1984 x 10000, K=1024)
    gemm64<AM_PLAIN, BM_PLAIN, OM_PRED><<<dim3(157, T, 1), 256>>>(
        p_hhist, H, W_fc, nullptr, nullptr, H, 0, b_fc, out, VV, H);

    (void)in_sizes; (void)n_in; (void)out_size;
}